// round 9
// baseline (speedup 1.0000x reference)
#include <cuda_runtime.h>
#include <cuda_bf16.h>
#include <cuda_fp16.h>

// Problem constants (SwitchingGRU1: B=256, T=512, H=128, S=8, N_SWITCH=6)
#define BB   256
#define TT   512
#define HH   128
#define SS   8
#define NSW  6

// Swizzled fp16 weights: 18 matrices of 128x128 halves (590 KB).
// Read pattern: thread (r = row, c = column-slice 0..3) reads, for gate g,
// k=0..3, the 8 halves of row r, cols [32c+8k .. 32c+8k+7] as one float4 at
// float4-index (g*NSW+sid)*2048 + k*512 + r*4 + c.
// Lane l = (r&7)*4 + c  ->  consecutive lanes read consecutive float4s.
__device__ __half g_wswz[3 * NSW * HH * HH];
// h history for the off-loop logit pass: [B][T][H] fp32 = 67 MB.
__device__ float g_hist[(size_t)BB * TT * HH];

__global__ void swz_kernel(const float* __restrict__ Wr,
                           const float* __restrict__ Wz,
                           const float* __restrict__ Wn) {
    int idx = blockIdx.x * blockDim.x + threadIdx.x;
    if (idx >= 3 * NSW * HH * HH) return;
    int m = idx >> 14;          // matrix id 0..17
    int i = (idx >> 7) & 127;   // row
    int j = idx & 127;          // col
    int g = m / NSW;
    int s = m % NSW;
    const float* W = (g == 0) ? Wr : (g == 1) ? Wz : Wn;
    float v = W[s * HH * HH + i * HH + j];
    int c = j >> 5;
    int k = (j >> 3) & 3;
    int w = j & 7;
    g_wswz[(size_t)m * 16384 + ((size_t)(k * 512 + i * 4 + c)) * 8 + w] =
        __float2half_rn(v);
}

// 512 threads: thread (r = tid>>2, c = tid&3) owns row r, column slice c.
__global__ __launch_bounds__(512, 2) void gru_kernel(
    const float* __restrict__ stim,     // [B,T,S]
    const int*   __restrict__ swid,     // [B,T]
    const float* __restrict__ mask,     // [B,T]
    const float* __restrict__ Win,      // [3H,S]
    const float* __restrict__ bin_,     // [3H]
    const float* __restrict__ bhr,      // [NSW,H]
    const float* __restrict__ bhz,      // [NSW,H]
    const float* __restrict__ bhn)      // [NSW,H]
{
    __shared__ __align__(16) float h_buf[2][HH];
    __shared__ __align__(16) float stim_sm[TT * SS];   // 16 KB
    __shared__ int   sid_sm[TT];
    __shared__ float mask_sm[TT];

    const int b   = blockIdx.x;
    const int tid = threadIdx.x;
    const int r   = tid >> 2;     // row 0..127
    const int c   = tid & 3;      // column slice 0..3

    // ---- one-time staging of the whole sequence for this batch ----
    {
        const float4* st4 = (const float4*)(stim + (size_t)b * TT * SS);
        float4* ss4 = (float4*)stim_sm;
        for (int e = tid; e < TT * SS / 4; e += 512) ss4[e] = st4[e];
        const int*   sb = swid + (size_t)b * TT;
        const float* mb = mask + (size_t)b * TT;
        for (int e = tid; e < TT; e += 512) {
            int s = sb[e];
            sid_sm[e]  = min(max(s, 0), NSW - 1);
            mask_sm[e] = mb[e];
        }
    }

    // ---- per-thread constants ----
    // Input-projection slice: dims {2c, 2c+1} of all 3 gates for row r.
    float wv[6];
#pragma unroll
    for (int g = 0; g < 3; g++) {
        wv[2 * g]     = Win[(g * HH + r) * SS + 2 * c];
        wv[2 * g + 1] = Win[(g * HH + r) * SS + 2 * c + 1];
    }
    // Static bias: slice 0 -> bin_r, 1 -> bin_z, 3 -> bin_n, 2 -> none.
    float bias_static = 0.0f;
    if (c == 0)      bias_static = bin_[r];
    else if (c == 1) bias_static = bin_[HH + r];
    else if (c == 3) bias_static = bin_[2 * HH + r];
    // Recurrent bias table: slice 0 -> b_hr, 1 -> b_hz, 2 -> b_hn, 3 -> 0.
    float bh_r[NSW];
    const float* bhp = (c == 0) ? bhr : (c == 1) ? bhz : (c == 2) ? bhn : nullptr;
#pragma unroll
    for (int s = 0; s < NSW; s++) bh_r[s] = bhp ? bhp[s * HH + r] : 0.0f;

    float h = 0.0f;                      // redundant in all 4 slice-threads
    if (c == 0) h_buf[0][r] = 0.0f;
    __syncthreads();

    const float4* __restrict__ Wf4 = (const float4*)g_wswz;
    float* __restrict__ hist_b = g_hist + (size_t)b * TT * HH;
    const int lane_off = r * 4 + c;

    for (int t = 0; t < TT; t++) {
        const int sid = sid_sm[t];

        // biases (added once per slice, pre-butterfly)
        const float binit = bias_static + bh_r[sid];
        float a0 = (c == 0) ? binit : 0.0f;   // r-gate pre-activation
        float a1 = (c == 1) ? binit : 0.0f;   // z-gate pre-activation
        float a2 = (c == 2) ? binit : 0.0f;   // n-gate recurrent part (+b_hn)
        float a3 = (c == 3) ? binit : 0.0f;   // n-gate input part

        // input-projection partials (2 dims per thread)
        const float sv0 = stim_sm[t * SS + 2 * c];
        const float sv1 = stim_sm[t * SS + 2 * c + 1];
        a0 = fmaf(wv[0], sv0, fmaf(wv[1], sv1, a0));
        a1 = fmaf(wv[2], sv0, fmaf(wv[3], sv1, a1));
        a3 = fmaf(wv[4], sv0, fmaf(wv[5], sv1, a3));

        // recurrent matvec: 32 cols x 3 gates, 12 coalesced LDG.128 (fp16)
        const float4* __restrict__ W0 = Wf4 + (size_t)(0 * NSW + sid) * 2048 + lane_off;
        const float4* __restrict__ W1 = Wf4 + (size_t)(1 * NSW + sid) * 2048 + lane_off;
        const float4* __restrict__ W2 = Wf4 + (size_t)(2 * NSW + sid) * 2048 + lane_off;
        const float4* h4 = (const float4*)h_buf[t & 1] + c * 8;
#pragma unroll
        for (int k = 0; k < 4; k++) {
            float4 ha = h4[2 * k];
            float4 hb = h4[2 * k + 1];
            float4 wraw0 = __ldg(W0 + k * 512);
            float4 wraw1 = __ldg(W1 + k * 512);
            float4 wraw2 = __ldg(W2 + k * 512);
            const __half2* p0 = (const __half2*)&wraw0;
            const __half2* p1 = (const __half2*)&wraw1;
            const __half2* p2 = (const __half2*)&wraw2;
            float hv[8] = {ha.x, ha.y, ha.z, ha.w, hb.x, hb.y, hb.z, hb.w};
#pragma unroll
            for (int q = 0; q < 4; q++) {
                float2 w0 = __half22float2(p0[q]);
                float2 w1 = __half22float2(p1[q]);
                float2 w2 = __half22float2(p2[q]);
                a0 = fmaf(w0.x, hv[2 * q], a0); a0 = fmaf(w0.y, hv[2 * q + 1], a0);
                a1 = fmaf(w1.x, hv[2 * q], a1); a1 = fmaf(w1.y, hv[2 * q + 1], a1);
                a2 = fmaf(w2.x, hv[2 * q], a2); a2 = fmaf(w2.y, hv[2 * q + 1], a2);
            }
        }

        // butterfly over the 4 column slices (lanes differ only in low 2 bits)
#pragma unroll
        for (int d = 1; d <= 2; d <<= 1) {
            a0 += __shfl_xor_sync(0xffffffffu, a0, d);
            a1 += __shfl_xor_sync(0xffffffffu, a1, d);
            a2 += __shfl_xor_sync(0xffffffffu, a2, d);
            a3 += __shfl_xor_sync(0xffffffffu, a3, d);
        }

        // gates (redundant in all 4 slice-threads)
        float rg = 1.0f / (1.0f + __expf(-a0));
        float zg = 1.0f / (1.0f + __expf(-a1));
        float ng = tanhf(a3 + rg * a2);
        float hnew = ng + zg * (h - ng);
        float m = mask_sm[t];
        h = h + m * (hnew - h);

        if (c == 0) h_buf[(t + 1) & 1][r] = h;
        if (c == 1) hist_b[(size_t)t * HH + r] = h;
        __syncthreads();      // h(t) visible; old-buffer reads complete
    }
}

// Off-loop logit pass: one warp per (b,t); out[b,t,:] = h @ Wo.T + bo.
__global__ __launch_bounds__(256) void logit_kernel(
    const float* __restrict__ Wo,       // [2,H]
    const float* __restrict__ bo,       // [2]
    float*       __restrict__ out)      // [B,T,2]
{
    const int warp = (blockIdx.x * 256 + threadIdx.x) >> 5;
    const int lane = threadIdx.x & 31;
    if (warp >= BB * TT) return;
    const float* hrow = g_hist + (size_t)warp * HH;
    float4 hv  = __ldg((const float4*)hrow + lane);
    float4 w0v = __ldg((const float4*)Wo + lane);
    float4 w1v = __ldg((const float4*)(Wo + HH) + lane);
    float p0 = hv.x * w0v.x + hv.y * w0v.y + hv.z * w0v.z + hv.w * w0v.w;
    float p1 = hv.x * w1v.x + hv.y * w1v.y + hv.z * w1v.z + hv.w * w1v.w;
#pragma unroll
    for (int o = 16; o; o >>= 1) {
        p0 += __shfl_down_sync(0xffffffffu, p0, o);
        p1 += __shfl_down_sync(0xffffffffu, p1, o);
    }
    if (lane == 0) {
        out[2 * warp]     = p0 + __ldg(bo);
        out[2 * warp + 1] = p1 + __ldg(bo + 1);
    }
}

extern "C" void kernel_launch(void* const* d_in, const int* in_sizes, int n_in,
                              void* d_out, int out_size) {
    const float* stim  = (const float*)d_in[0];
    const int*   swid  = (const int*)  d_in[1];
    const float* mask  = (const float*)d_in[2];
    const float* Win   = (const float*)d_in[3];
    const float* bin_  = (const float*)d_in[4];
    const float* W_hr  = (const float*)d_in[5];
    const float* W_hz  = (const float*)d_in[6];
    const float* W_hn  = (const float*)d_in[7];
    const float* b_hr  = (const float*)d_in[8];
    const float* b_hz  = (const float*)d_in[9];
    const float* b_hn  = (const float*)d_in[10];
    const float* Wo    = (const float*)d_in[11];
    const float* bo    = (const float*)d_in[12];
    float* out = (float*)d_out;

    const int total = 3 * NSW * HH * HH;
    swz_kernel<<<(total + 255) / 256, 256>>>(W_hr, W_hz, W_hn);
    gru_kernel<<<BB, 512>>>(stim, swid, mask, Win, bin_, b_hr, b_hz, b_hn);
    logit_kernel<<<(BB * TT * 32 + 255) / 256, 256>>>(Wo, bo, out);
}